// round 2
// baseline (speedup 1.0000x reference)
#include <cuda_runtime.h>
#include <cuda_bf16.h>
#include <math.h>
#include <stdint.h>

// Problem constants
#define B   8
#define T   16
#define CIN 3
#define HID 64
#define HW  64
#define PIX (HW*HW)          // 4096

#define KC   8               // input-channel chunk held in smem
#define INW  68              // padded input row width (1 left halo + 64 + 1 right halo + 2 pad)

// ---------------- scratch (no allocation allowed) ----------------
__device__ float g_xin[B*T*CIN*PIX];          // attention-scaled input
__device__ float g_h0[2][B*HID*PIX];          // layer0 hidden, double buffered
__device__ float g_c0[B*HID*PIX];             // layer0 cell
__device__ float g_h1[2][B*HID*PIX];          // layer1 hidden, double buffered
__device__ float g_c1[B*HID*PIX];             // layer1 cell

// ---------------- packed f32x2 helpers ----------------
__device__ __forceinline__ uint64_t pack2u(uint32_t lo, uint32_t hi) {
    uint64_t r; asm("mov.b64 %0, {%1,%2};" : "=l"(r) : "r"(lo), "r"(hi)); return r;
}
__device__ __forceinline__ uint64_t midpair(uint64_t a, uint64_t b) {
    // returns { hi(a), lo(b) }
    uint32_t alo, ahi, blo, bhi;
    asm("mov.b64 {%0,%1}, %2;" : "=r"(alo), "=r"(ahi) : "l"(a));
    asm("mov.b64 {%0,%1}, %2;" : "=r"(blo), "=r"(bhi) : "l"(b));
    return pack2u(ahi, blo);
}
__device__ __forceinline__ void fma2(uint64_t& d, uint64_t a, uint64_t w) {
    asm("fma.rn.f32x2 %0, %1, %2, %0;" : "+l"(d) : "l"(a), "l"(w));
}
__device__ __forceinline__ void unpack2(uint64_t v, float& lo, float& hi) {
    uint32_t l, h;
    asm("mov.b64 {%0,%1}, %2;" : "=r"(l), "=r"(h) : "l"(v));
    lo = __uint_as_float(l); hi = __uint_as_float(h);
}

// ---------------- attention + input scaling ----------------
__global__ void attention_kernel(const float* __restrict__ x,
                                 const float* __restrict__ w1,
                                 const float* __restrict__ w2,
                                 float* __restrict__ xin)
{
    const int bt = blockIdx.x;                 // 0..127
    const float* xp = x  + (long)bt * CIN * PIX;
    float*       xo = xin + (long)bt * CIN * PIX;

    __shared__ float s_sum[256], s_max[256];
    __shared__ float chAvg[CIN], chMax[CIN], scale[CIN];

    for (int c = 0; c < CIN; ++c) {
        float s = 0.f, m = -INFINITY;
        for (int i = threadIdx.x; i < PIX; i += 256) {
            float v = xp[c*PIX + i];
            s += v; m = fmaxf(m, v);
        }
        s_sum[threadIdx.x] = s; s_max[threadIdx.x] = m;
        __syncthreads();
        for (int off = 128; off > 0; off >>= 1) {
            if (threadIdx.x < off) {
                s_sum[threadIdx.x] += s_sum[threadIdx.x + off];
                s_max[threadIdx.x] = fmaxf(s_max[threadIdx.x], s_max[threadIdx.x + off]);
            }
            __syncthreads();
        }
        if (threadIdx.x == 0) { chAvg[c] = s_sum[0] / (float)PIX; chMax[c] = s_max[0]; }
        __syncthreads();
    }
    if (threadIdx.x == 0) {
        float ha = w1[0]*chAvg[0] + w1[1]*chAvg[1] + w1[2]*chAvg[2];
        float hm = w1[0]*chMax[0] + w1[1]*chMax[1] + w1[2]*chMax[2];
        ha = fmaxf(ha, 0.f); hm = fmaxf(hm, 0.f);
        float hs = ha + hm;
        for (int c = 0; c < CIN; ++c)
            scale[c] = 1.f / (1.f + expf(-w2[c]*hs));
    }
    __syncthreads();
    for (int c = 0; c < CIN; ++c)
        for (int i = threadIdx.x; i < PIX; i += 256)
            xo[c*PIX + i] = xp[c*PIX + i] * scale[c];
}

// ---------------- fused conv(3x3 SAME) + LSTM pointwise step ----------------
// grid: (16 row-tiles, 8 hidden-groups, 8 batches), 256 threads.
// Warp owns one hidden channel; lane owns adjacent column pair (2*lane, 2*lane+1)
// for 4 rows -> 4 gates x 4 rows of f32x2 accumulators (packed pairs).
__global__ __launch_bounds__(256)
void convlstm_step(const float* __restrict__ srcA, int CA, long sA,
                   const float* __restrict__ srcB, long sB,
                   int Cin,
                   const float* __restrict__ W,        // [4*HID, Cin, 3,3]
                   const float* __restrict__ bias,     // [4*HID]
                   float* __restrict__ cState,         // [B,HID,PIX] in/out
                   float* __restrict__ hOut,  long hOutStride,
                   float* __restrict__ hOut2, long hOut2Stride,
                   float* __restrict__ hFin,  float* __restrict__ cFin)
{
    const int b    = blockIdx.z;
    const int warp = threadIdx.x >> 5;
    const int lane = threadIdx.x & 31;
    const int j    = blockIdx.y * 8 + warp;    // hidden channel
    const int r0   = blockIdx.x * 4;           // first output row

    __shared__ __align__(16) float in_s[KC*6*INW];      // [kc][6 rows][68 cols]
    __shared__ __align__(16) float w_s[8*KC*9*8];       // [wj][kc][kk][gate*2 dup]

    uint64_t acc[4][4];                                 // [gate][row] packed pairs
    #pragma unroll
    for (int g = 0; g < 4; ++g)
        #pragma unroll
        for (int r = 0; r < 4; ++r) acc[g][r] = 0ull;

    const float* srcAb = srcA + (long)b * sA;
    const float* srcBb = srcB + (long)b * sB;

    for (int c0 = 0; c0 < Cin; c0 += KC) {
        const int kcCnt = min(KC, Cin - c0);
        __syncthreads();
        // ---- stage input tile (array col = global col + 1; zero pad) ----
        const int total = kcCnt * 6 * INW;
        for (int idx = threadIdx.x; idx < total; idx += 256) {
            int col = idx % INW;
            int row = (idx / INW) % 6;
            int kc  = idx / (INW*6);
            int c   = c0 + kc;
            int gr  = r0 + row - 1;
            int gc  = col - 1;
            float v = 0.f;
            if (gr >= 0 && gr < HW && gc >= 0 && gc < HW) {
                v = (c < CA) ? srcAb[(long)c      *PIX + gr*HW + gc]
                             : srcBb[(long)(c-CA) *PIX + gr*HW + gc];
            }
            in_s[idx] = v;
        }
        // ---- stage weights, each duplicated into a {w,w} pair ----
        const int wtotal = 8 * kcCnt * 9 * 8;   // wj * kc * kk * (4 gates x 2 dup)
        for (int idx = threadIdx.x; idx < wtotal; idx += 256) {
            int g   = (idx >> 1) & 3;
            int kk  = (idx >> 3) % 9;
            int kc  = (idx / 72) % kcCnt;
            int wj  = idx / (72 * kcCnt);
            int oc  = g*HID + blockIdx.y*8 + wj;
            float v = W[((long)oc*Cin + c0 + kc)*9 + kk];
            w_s[((wj*KC + kc)*9 + kk)*8 + (idx & 7)] = v;
        }
        __syncthreads();

        // ---- accumulate ----
        for (int kc = 0; kc < kcCnt; ++kc) {
            const float* rp = in_s + kc*6*INW + 2*lane;
            const float* wp = w_s + (warp*KC + kc)*72;
            #pragma unroll
            for (int ky = 0; ky < 3; ++ky) {
                // rows ky..ky+3: load packed pairs for kx = 0,1,2
                uint64_t Lr[4], Mr[4], Rr[4];
                #pragma unroll
                for (int r = 0; r < 4; ++r) {
                    uint64_t u01 = *(const uint64_t*)(rp + (r + ky)*INW);
                    uint64_t u23 = *(const uint64_t*)(rp + (r + ky)*INW + 2);
                    Lr[r] = u01;
                    Mr[r] = midpair(u01, u23);
                    Rr[r] = u23;
                }
                #pragma unroll
                for (int kx = 0; kx < 3; ++kx) {
                    const int kk = ky*3 + kx;
                    ulonglong2 wAB = *(const ulonglong2*)(wp + kk*8);      // {w0,w0},{w1,w1}
                    ulonglong2 wCD = *(const ulonglong2*)(wp + kk*8 + 4);  // {w2,w2},{w3,w3}
                    #pragma unroll
                    for (int r = 0; r < 4; ++r) {
                        uint64_t a = (kx == 0) ? Lr[r] : (kx == 1) ? Mr[r] : Rr[r];
                        fma2(acc[0][r], a, wAB.x);
                        fma2(acc[1][r], a, wAB.y);
                        fma2(acc[2][r], a, wCD.x);
                        fma2(acc[3][r], a, wCD.y);
                    }
                }
            }
        }
    }

    // ---- fused LSTM pointwise update (column pair per lane) ----
    const float bi = bias[j], bf = bias[HID + j], bo = bias[2*HID + j], bg = bias[3*HID + j];
    const long cBase = ((long)b*HID + j)*PIX;
    #pragma unroll
    for (int r = 0; r < 4; ++r) {
        const int  pix  = (r0 + r)*HW + 2*lane;
        const long cOff = cBase + pix;
        float i0,i1, f0,f1, o0,o1, g0,g1;
        unpack2(acc[0][r], i0, i1);
        unpack2(acc[1][r], f0, f1);
        unpack2(acc[2][r], o0, o1);
        unpack2(acc[3][r], g0, g1);

        float2 cOld = *(const float2*)(cState + cOff);

        float ig0 = 1.f/(1.f + __expf(-(i0 + bi)));
        float ig1 = 1.f/(1.f + __expf(-(i1 + bi)));
        float fg0 = 1.f/(1.f + __expf(-(f0 + bf)));
        float fg1 = 1.f/(1.f + __expf(-(f1 + bf)));
        float og0 = 1.f/(1.f + __expf(-(o0 + bo)));
        float og1 = 1.f/(1.f + __expf(-(o1 + bo)));
        float gg0 = tanhf(g0 + bg);
        float gg1 = tanhf(g1 + bg);

        float cN0 = fg0*cOld.x + ig0*gg0;
        float cN1 = fg1*cOld.y + ig1*gg1;
        float hN0 = og0*tanhf(cN0);
        float hN1 = og1*tanhf(cN1);

        *(float2*)(cState + cOff) = make_float2(cN0, cN1);
        *(float2*)(hOut + (long)b*hOutStride + (long)j*PIX + pix) = make_float2(hN0, hN1);
        if (hOut2) *(float2*)(hOut2 + (long)b*hOut2Stride + (long)j*PIX + pix) = make_float2(hN0, hN1);
        if (hFin)  *(float2*)(hFin + cBase + pix) = make_float2(hN0, hN1);
        if (cFin)  *(float2*)(cFin + cBase + pix) = make_float2(cN0, cN1);
    }
}

// ---------------- host ----------------
extern "C" void kernel_launch(void* const* d_in, const int* in_sizes, int n_in,
                              void* d_out, int out_size)
{
    const float* x       = (const float*)d_in[0];
    const float* att_w1  = (const float*)d_in[1];
    const float* att_w2  = (const float*)d_in[2];
    const float* conv_w0 = (const float*)d_in[3];
    const float* conv_b0 = (const float*)d_in[4];
    const float* conv_w1 = (const float*)d_in[5];
    const float* conv_b1 = (const float*)d_in[6];
    float* out = (float*)d_out;

    float *xin, *h0_0, *h0_1, *c0, *h1_0, *h1_1, *c1;
    cudaGetSymbolAddress((void**)&xin,  g_xin);
    cudaGetSymbolAddress((void**)&h0_0, g_h0);   h0_1 = h0_0 + (long)B*HID*PIX;
    cudaGetSymbolAddress((void**)&c0,   g_c0);
    cudaGetSymbolAddress((void**)&h1_0, g_h1);   h1_1 = h1_0 + (long)B*HID*PIX;
    cudaGetSymbolAddress((void**)&c1,   g_c1);

    const size_t stBytes = (size_t)B*HID*PIX*sizeof(float);
    cudaMemsetAsync(h0_0, 0, stBytes);
    cudaMemsetAsync(c0,   0, stBytes);
    cudaMemsetAsync(h1_0, 0, stBytes);
    cudaMemsetAsync(c1,   0, stBytes);

    attention_kernel<<<B*T, 256>>>(x, att_w1, att_w2, xin);

    float* h0buf[2] = {h0_0, h0_1};
    float* h1buf[2] = {h1_0, h1_1};

    float* out1  = out;                                  // [B,T,HID,PIX]
    float* h1fin = out + (long)B*T*HID*PIX;              // [B,HID,PIX]
    float* c1fin = h1fin + (long)B*HID*PIX;              // [B,HID,PIX]

    dim3 grid(HW/4, HID/8, B);

    for (int t = 0; t < T; ++t) {
        const int p = t & 1;
        // layer 0: in = [xin(t) (3ch) | h0], out -> h0(other parity), c0 in-place
        convlstm_step<<<grid, 256>>>(
            xin + (long)t*CIN*PIX, CIN, (long)T*CIN*PIX,
            h0buf[p], (long)HID*PIX,
            CIN + HID, conv_w0, conv_b0,
            c0,
            h0buf[p^1], (long)HID*PIX,
            nullptr, 0, nullptr, nullptr);
        // layer 1: in = [h0_new (64ch) | h1], out -> h1(other parity) + out1[:,t]
        convlstm_step<<<grid, 256>>>(
            h0buf[p^1], HID, (long)HID*PIX,
            h1buf[p], (long)HID*PIX,
            2*HID, conv_w1, conv_b1,
            c1,
            h1buf[p^1], (long)HID*PIX,
            out1 + (long)t*HID*PIX, (long)T*HID*PIX,
            (t == T-1) ? h1fin : nullptr,
            (t == T-1) ? c1fin : nullptr);
    }
}